// round 1
// baseline (speedup 1.0000x reference)
#include <cuda_runtime.h>

// CBFHalfspace collapses analytically:
//   A = [[-1,0,0...],[1,0,...],[0,-1,...],[0,1,...]]  (4x7), b = [1,1,1,1]
//   h(x) = b - A x = [1+x0, 1-x0, 1+x1, 1-x1]
//   grad(sum h) = -A.sum(0) = 0  -> Lfh = 0
//   h affine   -> Lf2h = 0, LgLfh = (0,0)
// Output row: [1+x0, 1-x0, 1+x1, 1-x1, 0, 0, 0, 0]. f, g are unused.

__global__ void __launch_bounds__(256)
cbf_kernel(const float* __restrict__ x, float4* __restrict__ out4, int n)
{
    int i = blockIdx.x * blockDim.x + threadIdx.x;
    if (i >= n) return;

    // Row stride is 7 floats (28 B) -> misaligned for float2; scalar loads.
    const float x0 = __ldg(&x[i * 7 + 0]);
    const float x1 = __ldg(&x[i * 7 + 1]);

    float4 h;
    h.x = 1.0f + x0;
    h.y = 1.0f - x0;
    h.z = 1.0f + x1;
    h.w = 1.0f - x1;

    out4[2 * i + 0] = h;
    out4[2 * i + 1] = make_float4(0.0f, 0.0f, 0.0f, 0.0f);
}

extern "C" void kernel_launch(void* const* d_in, const int* in_sizes, int n_in,
                              void* d_out, int out_size)
{
    const float* x = (const float*)d_in[0];   // (B, 7) float32
    // d_in[1] = f (7,), d_in[2] = g (7,2): analytically dead (zero contribution).
    float4* out4 = (float4*)d_out;            // (B, 8) float32 viewed as 2 float4/row

    const int n = in_sizes[0] / 7;            // B rows
    const int threads = 256;
    const int blocks = (n + threads - 1) / threads;
    cbf_kernel<<<blocks, threads>>>(x, out4, n);
}